// round 15
// baseline (speedup 1.0000x reference)
#include <cuda_runtime.h>
#include <cuda_fp16.h>
#include <cstdint>

#define SEQ 4096
#define DIM 1024
typedef __half fp16;

// ---------------- scratch (device globals; allocations forbidden) ----------
__device__ fp16 g_q16[SEQ * DIM], g_k16[SEQ * DIM], g_v16[SEQ * DIM];
__device__ fp16 g_Wq16[DIM * DIM], g_Wk16[DIM * DIM], g_Wv16[DIM * DIM];
__device__ fp16 g_qp16[SEQ * DIM];
__device__ fp16 g_kp16[SEQ * DIM];
__device__ fp16 g_vt16[DIM * SEQ];                    // vp TRANSPOSED [DIM, SEQ]
__device__ fp16 g_sc16[(size_t)SEQ * SEQ];            // raw scores, fp16
__device__ fp16 g_a16[(size_t)SEQ * SEQ];             // softmax+bias, fp16

// ---------------- helpers ---------------------------------------------------
__device__ __forceinline__ uint32_t smem_u32(const void* p) {
    uint32_t a;
    asm("{ .reg .u64 t; cvta.to.shared.u64 t, %1; cvt.u32.u64 %0, t; }"
        : "=r"(a) : "l"(p));
    return a;
}
__device__ __forceinline__ void cpasync16(uint32_t saddr, const void* gptr) {
    asm volatile("cp.async.cg.shared.global [%0], [%1], 16;"
                 :: "r"(saddr), "l"(gptr) : "memory");
}
#define CP_COMMIT() asm volatile("cp.async.commit_group;" ::: "memory")
#define CP_WAIT1()  asm volatile("cp.async.wait_group 1;" ::: "memory")

#define LDSM_X4(r, addr)                                                        \
    asm volatile("ldmatrix.sync.aligned.m8n8.x4.shared.b16 {%0,%1,%2,%3}, [%4];"\
                 : "=r"((r)[0]), "=r"((r)[1]), "=r"((r)[2]), "=r"((r)[3])       \
                 : "r"(addr))
#define LDSM_X2(r, addr)                                                        \
    asm volatile("ldmatrix.sync.aligned.m8n8.x2.shared.b16 {%0,%1}, [%2];"      \
                 : "=r"((r)[0]), "=r"((r)[1]) : "r"(addr))
#define MMA_F16(c, a, b)                                                        \
    asm volatile("mma.sync.aligned.m16n8k16.row.col.f32.f16.f16.f32 "           \
                 "{%0,%1,%2,%3}, {%4,%5,%6,%7}, {%8,%9}, {%0,%1,%2,%3};"        \
                 : "+f"((c)[0]), "+f"((c)[1]), "+f"((c)[2]), "+f"((c)[3])       \
                 : "r"((a)[0]), "r"((a)[1]), "r"((a)[2]), "r"((a)[3]),          \
                   "r"((b)[0]), "r"((b)[1]))

// ---------------- batched fp32 -> fp16 convert (6 tensors, one launch) -------
__global__ __launch_bounds__(256)
void cvt6_kernel(const float* __restrict__ x0, const float* __restrict__ x1,
                 const float* __restrict__ x2, const float* __restrict__ x3,
                 const float* __restrict__ x4, const float* __restrict__ x5,
                 fp16* __restrict__ y0, fp16* __restrict__ y1,
                 fp16* __restrict__ y2, fp16* __restrict__ y3,
                 fp16* __restrict__ y4, fp16* __restrict__ y5,
                 int nBig, int nSmall) {
    const int t = blockIdx.y;
    const int n4 = (t < 3) ? nBig : nSmall;
    int i = blockIdx.x * 256 + threadIdx.x;
    if (i >= n4) return;
    const float* xs[6] = {x0, x1, x2, x3, x4, x5};
    fp16* ys[6] = {y0, y1, y2, y3, y4, y5};
    float4 v = reinterpret_cast<const float4*>(xs[t])[i];
    __half2* hp = reinterpret_cast<__half2*>(ys[t]) + 2 * (size_t)i;
    hp[0] = __half2(__float2half_rn(v.x), __float2half_rn(v.y));
    hp[1] = __half2(__float2half_rn(v.z), __float2half_rn(v.w));
}

// ---------------- shared mainloop pieces -------------------------------------
#define TSTRIDE 72                            // 64 halves + 8 pad (144 B rows)
#define TILEB (128 * TSTRIDE * 2)             // 18432 B
#define STAGEB (2 * TILEB)                    // A, B
#define SMEM_SZ (3 * STAGEB)                  // 110592 B

// ---------------- fp16 mma.sync GEMM, BK=64, 1 term --------------------------
// EPI 0: Cf = acc (fp32)                      — out GEMM
// EPI 1: Ch = fp16(acc + bias) row-major      — q/k projections
// EPI 2: Ch = fp16(acc + bias) TRANSPOSED     — v projection ([Nn, SEQ])
// EPI 3: Ch = fp16(acc) row-major             — scores
template <int EPI>
__global__ __launch_bounds__(256, 2)
void gemm_mma(const fp16* __restrict__ A, const fp16* __restrict__ B,
              const float* __restrict__ bias, float* __restrict__ Cf,
              fp16* __restrict__ Ch, int Nn, int K) {
    extern __shared__ char smem_raw[];
    const uint32_t sbase = smem_u32(smem_raw);

    const int tid = threadIdx.x;
    const int wid = tid >> 5;
    const int lane = tid & 31;
    const int mBase = blockIdx.y * 128;
    const int nBase = blockIdx.x * 128;
    const int warp_m = (wid & 1) * 64;
    const int warp_n = (wid >> 1) * 32;

    const int ldRow = tid >> 3;
    const int ldKc = (tid & 7) * 8;
    const uint32_t sOff = ldRow * (TSTRIDE * 2) + ldKc * 2;

    const fp16* gA = A + (size_t)mBase * K;
    const fp16* gB = B + (size_t)nBase * K;

    const uint32_t aOff = (warp_m + (lane & 15)) * (TSTRIDE * 2) + (lane >> 4) * 16;
    const int bl16 = lane & 15;
    const uint32_t bOff = (warp_n + (bl16 & 7)) * (TSTRIDE * 2) + (bl16 >> 3) * 16;

    float acc[4][4][4];
#pragma unroll
    for (int i = 0; i < 4; i++)
#pragma unroll
        for (int j = 0; j < 4; j++)
#pragma unroll
            for (int p = 0; p < 4; p++) acc[i][j][p] = 0.f;

    const int NIT = K >> 6;

#pragma unroll
    for (int s = 0; s < 2; s++) {
        const uint32_t nb = sbase + s * STAGEB;
        const int kt = s * 64;
#pragma unroll
        for (int j = 0; j < 4; j++) {
            cpasync16(nb + sOff + j * 32 * (TSTRIDE * 2),
                      gA + (size_t)(ldRow + j * 32) * K + kt + ldKc);
            cpasync16(nb + TILEB + sOff + j * 32 * (TSTRIDE * 2),
                      gB + (size_t)(ldRow + j * 32) * K + kt + ldKc);
        }
        CP_COMMIT();
    }

    int stage = 0;
    for (int it = 0; it < NIT; it++) {
        CP_WAIT1();
        __syncthreads();

        if (it + 2 < NIT) {
            int ns = stage + 2; if (ns >= 3) ns -= 3;
            const uint32_t nb = sbase + ns * STAGEB;
            const int kt = (it + 2) * 64;
#pragma unroll
            for (int j = 0; j < 4; j++) {
                cpasync16(nb + sOff + j * 32 * (TSTRIDE * 2),
                          gA + (size_t)(ldRow + j * 32) * K + kt + ldKc);
                cpasync16(nb + TILEB + sOff + j * 32 * (TSTRIDE * 2),
                          gB + (size_t)(ldRow + j * 32) * K + kt + ldKc);
            }
        }
        CP_COMMIT();

        const uint32_t cb = sbase + stage * STAGEB;
#pragma unroll
        for (int ks = 0; ks < 4; ks++) {
            uint32_t af[4][4], bf[4][2];
            const uint32_t abase = cb + aOff + ks * 32;
            const uint32_t bbase = cb + TILEB + bOff + ks * 32;
#pragma unroll
            for (int mf = 0; mf < 4; mf++)
                LDSM_X4(af[mf], abase + mf * (16 * TSTRIDE * 2));
#pragma unroll
            for (int nf = 0; nf < 4; nf++)
                LDSM_X2(bf[nf], bbase + nf * (8 * TSTRIDE * 2));
#pragma unroll
            for (int mf = 0; mf < 4; mf++)
#pragma unroll
                for (int nf = 0; nf < 4; nf++) MMA_F16(acc[mf][nf], af[mf], bf[nf]);
        }
        if (++stage == 3) stage = 0;
    }

    // ------------- epilogue -------------
    if (EPI == 0) {
#pragma unroll
        for (int mf = 0; mf < 4; mf++)
#pragma unroll
            for (int nf = 0; nf < 4; nf++) {
                int row = mBase + warp_m + mf * 16 + (lane >> 2);
                int col = nBase + warp_n + nf * 8 + 2 * (lane & 3);
                float2 v0 = {acc[mf][nf][0], acc[mf][nf][1]};
                float2 v1 = {acc[mf][nf][2], acc[mf][nf][3]};
                *reinterpret_cast<float2*>(&Cf[(size_t)row * Nn + col]) = v0;
                *reinterpret_cast<float2*>(&Cf[(size_t)(row + 8) * Nn + col]) = v1;
            }
    } else if (EPI == 1) {
#pragma unroll
        for (int mf = 0; mf < 4; mf++)
#pragma unroll
            for (int nf = 0; nf < 4; nf++) {
                int row = mBase + warp_m + mf * 16 + (lane >> 2);
                int col = nBase + warp_n + nf * 8 + 2 * (lane & 3);
                float b0 = bias[col], b1 = bias[col + 1];
                *reinterpret_cast<__half2*>(&Ch[(size_t)row * Nn + col]) =
                    __half2(__float2half_rn(acc[mf][nf][0] + b0),
                            __float2half_rn(acc[mf][nf][1] + b1));
                *reinterpret_cast<__half2*>(&Ch[(size_t)(row + 8) * Nn + col]) =
                    __half2(__float2half_rn(acc[mf][nf][2] + b0),
                            __float2half_rn(acc[mf][nf][3] + b1));
            }
    } else if (EPI == 3) {
#pragma unroll
        for (int mf = 0; mf < 4; mf++)
#pragma unroll
            for (int nf = 0; nf < 4; nf++) {
                int row = mBase + warp_m + mf * 16 + (lane >> 2);
                int col = nBase + warp_n + nf * 8 + 2 * (lane & 3);
                *reinterpret_cast<__half2*>(&Ch[(size_t)row * Nn + col]) =
                    __half2(__float2half_rn(acc[mf][nf][0]),
                            __float2half_rn(acc[mf][nf][1]));
                *reinterpret_cast<__half2*>(&Ch[(size_t)(row + 8) * Nn + col]) =
                    __half2(__float2half_rn(acc[mf][nf][2]),
                            __float2half_rn(acc[mf][nf][3]));
            }
    } else {
        // EPI 2: transpose via SMEM then coalesced fp16 store (Ch is [Nn, SEQ])
        float* sb = reinterpret_cast<float*>(smem_raw);
        __syncthreads();
#pragma unroll
        for (int mf = 0; mf < 4; mf++)
#pragma unroll
            for (int nf = 0; nf < 4; nf++) {
                int rl = warp_m + mf * 16 + (lane >> 2);
                int cl = warp_n + nf * 8 + 2 * (lane & 3);
                float b0 = bias[nBase + cl], b1 = bias[nBase + cl + 1];
                sb[cl * 129 + rl] = acc[mf][nf][0] + b0;
                sb[(cl + 1) * 129 + rl] = acc[mf][nf][1] + b1;
                sb[cl * 129 + rl + 8] = acc[mf][nf][2] + b0;
                sb[(cl + 1) * 129 + rl + 8] = acc[mf][nf][3] + b1;
            }
        __syncthreads();
        const int col = tid >> 1;
        const int half = (tid & 1) * 64;
        size_t base = (size_t)(nBase + col) * SEQ + mBase + half;
#pragma unroll
        for (int r = 0; r < 64; r += 2) {
            float x0 = sb[col * 129 + half + r];
            float x1 = sb[col * 129 + half + r + 1];
            *reinterpret_cast<__half2*>(&Ch[base + r]) =
                __half2(__float2half_rn(x0), __float2half_rn(x1));
        }
    }
}

// --------- register-resident softmax(scale*scores) + bias -> fp16 ------------
// 256 threads, 16 values/thread held in registers across all phases.
// Reductions: warp shuffle + 8-word smem stage; 2 block barriers total.
__global__ __launch_bounds__(256)
void softmax_bias_f16(const fp16* __restrict__ sc, const float* __restrict__ bias,
                      fp16* __restrict__ ah, float scale) {
    __shared__ float redmax[8];
    __shared__ float redsum[8];
    const int row = blockIdx.x;
    const int tid = threadIdx.x;
    const int wid = tid >> 5;
    const int lane = tid & 31;
    const fp16* rp = sc + (size_t)row * SEQ;
    const float* bp = bias + (size_t)row * SEQ;

    // load 16 values (two 16B segments, coalesced), convert + scale
    float v[16];
    float lmax = -1e30f;
#pragma unroll
    for (int seg = 0; seg < 2; seg++) {
        const int idx = seg * 2048 + tid * 8;
        uint4 raw = *reinterpret_cast<const uint4*>(rp + idx);
        const __half2* h = reinterpret_cast<const __half2*>(&raw);
#pragma unroll
        for (int j = 0; j < 4; j++) {
            float2 f = __half22float2(h[j]);
            v[seg * 8 + 2 * j] = f.x * scale;
            v[seg * 8 + 2 * j + 1] = f.y * scale;
        }
    }
#pragma unroll
    for (int i = 0; i < 16; i++) lmax = fmaxf(lmax, v[i]);
#pragma unroll
    for (int s = 16; s > 0; s >>= 1)
        lmax = fmaxf(lmax, __shfl_xor_sync(0xFFFFFFFFu, lmax, s));
    if (lane == 0) redmax[wid] = lmax;
    __syncthreads();
    float mx = redmax[0];
#pragma unroll
    for (int w = 1; w < 8; w++) mx = fmaxf(mx, redmax[w]);

    // exp in registers + sum
    float lsum = 0.f;
#pragma unroll
    for (int i = 0; i < 16; i++) {
        v[i] = __expf(v[i] - mx);
        lsum += v[i];
    }
#pragma unroll
    for (int s = 16; s > 0; s >>= 1)
        lsum += __shfl_xor_sync(0xFFFFFFFFu, lsum, s);
    if (lane == 0) redsum[wid] = lsum;
    __syncthreads();
    float tot = redsum[0];
#pragma unroll
    for (int w = 1; w < 8; w++) tot += redsum[w];
    const float inv = 1.0f / tot;

    // normalize + bias + fp16 store
#pragma unroll
    for (int seg = 0; seg < 2; seg++) {
        const int idx = seg * 2048 + tid * 8;
        float4 b0 = *reinterpret_cast<const float4*>(bp + idx);
        float4 b1 = *reinterpret_cast<const float4*>(bp + idx + 4);
        const float* vv = v + seg * 8;
        __half2 hv[4];
        hv[0] = __half2(__float2half_rn(vv[0] * inv + b0.x),
                        __float2half_rn(vv[1] * inv + b0.y));
        hv[1] = __half2(__float2half_rn(vv[2] * inv + b0.z),
                        __float2half_rn(vv[3] * inv + b0.w));
        hv[2] = __half2(__float2half_rn(vv[4] * inv + b1.x),
                        __float2half_rn(vv[5] * inv + b1.y));
        hv[3] = __half2(__float2half_rn(vv[6] * inv + b1.z),
                        __float2half_rn(vv[7] * inv + b1.w));
        *reinterpret_cast<uint4*>(ah + (size_t)row * SEQ + idx) =
            *reinterpret_cast<uint4*>(hv);
    }
}

// ---------------------------------------------------------------------------
extern "C" void kernel_launch(void* const* d_in, const int* in_sizes, int n_in,
                              void* d_out, int out_size) {
    const float* q = (const float*)d_in[0];
    const float* k = (const float*)d_in[1];
    const float* v = (const float*)d_in[2];
    const float* bias = (const float*)d_in[3];
    const float* Wq = (const float*)d_in[4];
    const float* bq = (const float*)d_in[5];
    const float* Wk = (const float*)d_in[6];
    const float* bk = (const float*)d_in[7];
    const float* Wv = (const float*)d_in[8];
    const float* bv = (const float*)d_in[9];
    float* out = (float*)d_out;

    fp16 *q16, *k16, *v16, *Wq16, *Wk16, *Wv16;
    fp16 *qp16, *kp16, *vt16, *sc16, *a16;
    cudaGetSymbolAddress((void**)&q16, g_q16);   cudaGetSymbolAddress((void**)&k16, g_k16);
    cudaGetSymbolAddress((void**)&v16, g_v16);
    cudaGetSymbolAddress((void**)&Wq16, g_Wq16); cudaGetSymbolAddress((void**)&Wk16, g_Wk16);
    cudaGetSymbolAddress((void**)&Wv16, g_Wv16);
    cudaGetSymbolAddress((void**)&qp16, g_qp16); cudaGetSymbolAddress((void**)&kp16, g_kp16);
    cudaGetSymbolAddress((void**)&vt16, g_vt16); cudaGetSymbolAddress((void**)&sc16, g_sc16);
    cudaGetSymbolAddress((void**)&a16, g_a16);

    cudaFuncSetAttribute(gemm_mma<0>, cudaFuncAttributeMaxDynamicSharedMemorySize, SMEM_SZ);
    cudaFuncSetAttribute(gemm_mma<1>, cudaFuncAttributeMaxDynamicSharedMemorySize, SMEM_SZ);
    cudaFuncSetAttribute(gemm_mma<2>, cudaFuncAttributeMaxDynamicSharedMemorySize, SMEM_SZ);
    cudaFuncSetAttribute(gemm_mma<3>, cudaFuncAttributeMaxDynamicSharedMemorySize, SMEM_SZ);

    // one-time side streams + events (validated fork/join pattern, round 12)
    static cudaStream_t s1 = nullptr, s2 = nullptr;
    static cudaEvent_t e0 = nullptr, e1 = nullptr, e2 = nullptr;
    if (!s1) {
        cudaStreamCreateWithFlags(&s1, cudaStreamNonBlocking);
        cudaStreamCreateWithFlags(&s2, cudaStreamNonBlocking);
        cudaEventCreateWithFlags(&e0, cudaEventDisableTiming);
        cudaEventCreateWithFlags(&e1, cudaEventDisableTiming);
        cudaEventCreateWithFlags(&e2, cudaEventDisableTiming);
    }

    const float scale = 0.03125f;  // 1024^-0.5  (applied in softmax)
    dim3 blk(256);

    // one batched convert launch: q,k,v (big) + Wq,Wk,Wv (small)  [stream 0]
    const int nBig = SEQ * DIM / 4, nSmall = DIM * DIM / 4;
    cvt6_kernel<<<dim3(nBig / 256, 6), blk>>>(q, k, v, Wq, Wk, Wv,
                                              q16, k16, v16, Wq16, Wk16, Wv16,
                                              nBig, nSmall);
    cudaEventRecord(e0, 0);

    dim3 gProj(DIM / 128, SEQ / 128);
    // q-projection on main stream
    gemm_mma<1><<<gProj, blk, SMEM_SZ>>>(q16, Wq16, bq, nullptr, qp16, DIM, DIM);
    // k-projection on s1 (concurrent with q)
    cudaStreamWaitEvent(s1, e0, 0);
    gemm_mma<1><<<gProj, blk, SMEM_SZ, s1>>>(k16, Wk16, bk, nullptr, kp16, DIM, DIM);
    cudaEventRecord(e1, s1);
    // v-projection on s2 (concurrent with q/k AND with scores/softmax below)
    cudaStreamWaitEvent(s2, e0, 0);
    gemm_mma<2><<<gProj, blk, SMEM_SZ, s2>>>(v16, Wv16, bv, nullptr, vt16, DIM, DIM);
    cudaEventRecord(e2, s2);

    // scores = qp @ kp^T -> fp16 (needs q-proj [stream order] + k-proj [event])
    cudaStreamWaitEvent(0, e1, 0);
    dim3 gScore(SEQ / 128, SEQ / 128);
    gemm_mma<3><<<gScore, blk, SMEM_SZ>>>(qp16, kp16, nullptr, nullptr, sc16,
                                          SEQ, DIM);

    // softmax(scale * scores) + bias -> fp16 att (register-resident)
    softmax_bias_f16<<<SEQ, blk>>>(sc16, bias, a16, scale);

    // out = att @ vp (needs v-proj via event)
    cudaStreamWaitEvent(0, e2, 0);
    dim3 gOut(DIM / 128, SEQ / 128);
    gemm_mma<0><<<gOut, blk, SMEM_SZ>>>(a16, vt16, nullptr, out, nullptr,
                                        DIM, SEQ);
}

// round 16
// speedup vs baseline: 1.5583x; 1.5583x over previous
#include <cuda_runtime.h>
#include <cuda_fp16.h>
#include <cstdint>

#define SEQ 4096
#define DIM 1024
typedef __half fp16;

// ---------------- scratch (device globals; allocations forbidden) ----------
__device__ fp16 g_q16[SEQ * DIM], g_k16[SEQ * DIM], g_v16[SEQ * DIM];
__device__ fp16 g_Wq16[DIM * DIM], g_Wk16[DIM * DIM], g_Wv16[DIM * DIM];
__device__ fp16 g_qp16[SEQ * DIM];
__device__ fp16 g_kp16[SEQ * DIM];
__device__ fp16 g_vt16[DIM * SEQ];                    // vp TRANSPOSED [DIM, SEQ]
__device__ fp16 g_sc16[(size_t)SEQ * SEQ];            // raw scores, fp16
__device__ fp16 g_a16[(size_t)SEQ * SEQ];             // softmax+bias, fp16

// ---------------- helpers ---------------------------------------------------
__device__ __forceinline__ uint32_t smem_u32(const void* p) {
    uint32_t a;
    asm("{ .reg .u64 t; cvta.to.shared.u64 t, %1; cvt.u32.u64 %0, t; }"
        : "=r"(a) : "l"(p));
    return a;
}
__device__ __forceinline__ void cpasync16(uint32_t saddr, const void* gptr) {
    asm volatile("cp.async.cg.shared.global [%0], [%1], 16;"
                 :: "r"(saddr), "l"(gptr) : "memory");
}
#define CP_COMMIT() asm volatile("cp.async.commit_group;" ::: "memory")
#define CP_WAIT1()  asm volatile("cp.async.wait_group 1;" ::: "memory")

#define LDSM_X4(r, addr)                                                        \
    asm volatile("ldmatrix.sync.aligned.m8n8.x4.shared.b16 {%0,%1,%2,%3}, [%4];"\
                 : "=r"((r)[0]), "=r"((r)[1]), "=r"((r)[2]), "=r"((r)[3])       \
                 : "r"(addr))
#define LDSM_X2(r, addr)                                                        \
    asm volatile("ldmatrix.sync.aligned.m8n8.x2.shared.b16 {%0,%1}, [%2];"      \
                 : "=r"((r)[0]), "=r"((r)[1]) : "r"(addr))
#define MMA_F16(c, a, b)                                                        \
    asm volatile("mma.sync.aligned.m16n8k16.row.col.f32.f16.f16.f32 "           \
                 "{%0,%1,%2,%3}, {%4,%5,%6,%7}, {%8,%9}, {%0,%1,%2,%3};"        \
                 : "+f"((c)[0]), "+f"((c)[1]), "+f"((c)[2]), "+f"((c)[3])       \
                 : "r"((a)[0]), "r"((a)[1]), "r"((a)[2]), "r"((a)[3]),          \
                   "r"((b)[0]), "r"((b)[1]))

// ---------------- batched fp32 -> fp16 convert (6 tensors, one launch) -------
__global__ __launch_bounds__(256)
void cvt6_kernel(const float* __restrict__ x0, const float* __restrict__ x1,
                 const float* __restrict__ x2, const float* __restrict__ x3,
                 const float* __restrict__ x4, const float* __restrict__ x5,
                 fp16* __restrict__ y0, fp16* __restrict__ y1,
                 fp16* __restrict__ y2, fp16* __restrict__ y3,
                 fp16* __restrict__ y4, fp16* __restrict__ y5,
                 int nBig, int nSmall) {
    const int t = blockIdx.y;
    const int n4 = (t < 3) ? nBig : nSmall;
    int i = blockIdx.x * 256 + threadIdx.x;
    if (i >= n4) return;
    const float* xs[6] = {x0, x1, x2, x3, x4, x5};
    fp16* ys[6] = {y0, y1, y2, y3, y4, y5};
    float4 v = reinterpret_cast<const float4*>(xs[t])[i];
    __half2* hp = reinterpret_cast<__half2*>(ys[t]) + 2 * (size_t)i;
    hp[0] = __half2(__float2half_rn(v.x), __float2half_rn(v.y));
    hp[1] = __half2(__float2half_rn(v.z), __float2half_rn(v.w));
}

// ---------------- shared mainloop pieces -------------------------------------
#define TSTRIDE 72                            // 64 halves + 8 pad (144 B rows)
#define TILEB (128 * TSTRIDE * 2)             // 18432 B
#define STAGEB (2 * TILEB)                    // A, B
#define SMEM_SZ (3 * STAGEB)                  // 110592 B

// ---------------- fp16 mma.sync GEMM, BK=64, 1 term --------------------------
// EPI 0: Cf = acc (fp32)                      — out GEMM
// EPI 1: Ch = fp16(acc + bias) row-major      — q/k projections
// EPI 2: Ch = fp16(acc + bias) TRANSPOSED     — v projection ([Nn, SEQ])
// EPI 3: Ch = fp16(acc) row-major             — scores
template <int EPI>
__global__ __launch_bounds__(256, 2)
void gemm_mma(const fp16* __restrict__ A, const fp16* __restrict__ B,
              const float* __restrict__ bias, float* __restrict__ Cf,
              fp16* __restrict__ Ch, int Nn, int K) {
    extern __shared__ char smem_raw[];
    const uint32_t sbase = smem_u32(smem_raw);

    const int tid = threadIdx.x;
    const int wid = tid >> 5;
    const int lane = tid & 31;
    const int mBase = blockIdx.y * 128;
    const int nBase = blockIdx.x * 128;
    const int warp_m = (wid & 1) * 64;
    const int warp_n = (wid >> 1) * 32;

    const int ldRow = tid >> 3;
    const int ldKc = (tid & 7) * 8;
    const uint32_t sOff = ldRow * (TSTRIDE * 2) + ldKc * 2;

    const fp16* gA = A + (size_t)mBase * K;
    const fp16* gB = B + (size_t)nBase * K;

    const uint32_t aOff = (warp_m + (lane & 15)) * (TSTRIDE * 2) + (lane >> 4) * 16;
    const int bl16 = lane & 15;
    const uint32_t bOff = (warp_n + (bl16 & 7)) * (TSTRIDE * 2) + (bl16 >> 3) * 16;

    float acc[4][4][4];
#pragma unroll
    for (int i = 0; i < 4; i++)
#pragma unroll
        for (int j = 0; j < 4; j++)
#pragma unroll
            for (int p = 0; p < 4; p++) acc[i][j][p] = 0.f;

    const int NIT = K >> 6;

#pragma unroll
    for (int s = 0; s < 2; s++) {
        const uint32_t nb = sbase + s * STAGEB;
        const int kt = s * 64;
#pragma unroll
        for (int j = 0; j < 4; j++) {
            cpasync16(nb + sOff + j * 32 * (TSTRIDE * 2),
                      gA + (size_t)(ldRow + j * 32) * K + kt + ldKc);
            cpasync16(nb + TILEB + sOff + j * 32 * (TSTRIDE * 2),
                      gB + (size_t)(ldRow + j * 32) * K + kt + ldKc);
        }
        CP_COMMIT();
    }

    int stage = 0;
    for (int it = 0; it < NIT; it++) {
        CP_WAIT1();
        __syncthreads();

        if (it + 2 < NIT) {
            int ns = stage + 2; if (ns >= 3) ns -= 3;
            const uint32_t nb = sbase + ns * STAGEB;
            const int kt = (it + 2) * 64;
#pragma unroll
            for (int j = 0; j < 4; j++) {
                cpasync16(nb + sOff + j * 32 * (TSTRIDE * 2),
                          gA + (size_t)(ldRow + j * 32) * K + kt + ldKc);
                cpasync16(nb + TILEB + sOff + j * 32 * (TSTRIDE * 2),
                          gB + (size_t)(ldRow + j * 32) * K + kt + ldKc);
            }
        }
        CP_COMMIT();

        const uint32_t cb = sbase + stage * STAGEB;
#pragma unroll
        for (int ks = 0; ks < 4; ks++) {
            uint32_t af[4][4], bf[4][2];
            const uint32_t abase = cb + aOff + ks * 32;
            const uint32_t bbase = cb + TILEB + bOff + ks * 32;
#pragma unroll
            for (int mf = 0; mf < 4; mf++)
                LDSM_X4(af[mf], abase + mf * (16 * TSTRIDE * 2));
#pragma unroll
            for (int nf = 0; nf < 4; nf++)
                LDSM_X2(bf[nf], bbase + nf * (8 * TSTRIDE * 2));
#pragma unroll
            for (int mf = 0; mf < 4; mf++)
#pragma unroll
                for (int nf = 0; nf < 4; nf++) MMA_F16(acc[mf][nf], af[mf], bf[nf]);
        }
        if (++stage == 3) stage = 0;
    }

    // ------------- epilogue -------------
    if (EPI == 0) {
#pragma unroll
        for (int mf = 0; mf < 4; mf++)
#pragma unroll
            for (int nf = 0; nf < 4; nf++) {
                int row = mBase + warp_m + mf * 16 + (lane >> 2);
                int col = nBase + warp_n + nf * 8 + 2 * (lane & 3);
                float2 v0 = {acc[mf][nf][0], acc[mf][nf][1]};
                float2 v1 = {acc[mf][nf][2], acc[mf][nf][3]};
                *reinterpret_cast<float2*>(&Cf[(size_t)row * Nn + col]) = v0;
                *reinterpret_cast<float2*>(&Cf[(size_t)(row + 8) * Nn + col]) = v1;
            }
    } else if (EPI == 1) {
#pragma unroll
        for (int mf = 0; mf < 4; mf++)
#pragma unroll
            for (int nf = 0; nf < 4; nf++) {
                int row = mBase + warp_m + mf * 16 + (lane >> 2);
                int col = nBase + warp_n + nf * 8 + 2 * (lane & 3);
                float b0 = bias[col], b1 = bias[col + 1];
                *reinterpret_cast<__half2*>(&Ch[(size_t)row * Nn + col]) =
                    __half2(__float2half_rn(acc[mf][nf][0] + b0),
                            __float2half_rn(acc[mf][nf][1] + b1));
                *reinterpret_cast<__half2*>(&Ch[(size_t)(row + 8) * Nn + col]) =
                    __half2(__float2half_rn(acc[mf][nf][2] + b0),
                            __float2half_rn(acc[mf][nf][3] + b1));
            }
    } else if (EPI == 3) {
#pragma unroll
        for (int mf = 0; mf < 4; mf++)
#pragma unroll
            for (int nf = 0; nf < 4; nf++) {
                int row = mBase + warp_m + mf * 16 + (lane >> 2);
                int col = nBase + warp_n + nf * 8 + 2 * (lane & 3);
                *reinterpret_cast<__half2*>(&Ch[(size_t)row * Nn + col]) =
                    __half2(__float2half_rn(acc[mf][nf][0]),
                            __float2half_rn(acc[mf][nf][1]));
                *reinterpret_cast<__half2*>(&Ch[(size_t)(row + 8) * Nn + col]) =
                    __half2(__float2half_rn(acc[mf][nf][2]),
                            __float2half_rn(acc[mf][nf][3]));
            }
    } else {
        // EPI 2: transpose via SMEM then coalesced fp16 store (Ch is [Nn, SEQ])
        float* sb = reinterpret_cast<float*>(smem_raw);
        __syncthreads();
#pragma unroll
        for (int mf = 0; mf < 4; mf++)
#pragma unroll
            for (int nf = 0; nf < 4; nf++) {
                int rl = warp_m + mf * 16 + (lane >> 2);
                int cl = warp_n + nf * 8 + 2 * (lane & 3);
                float b0 = bias[nBase + cl], b1 = bias[nBase + cl + 1];
                sb[cl * 129 + rl] = acc[mf][nf][0] + b0;
                sb[(cl + 1) * 129 + rl] = acc[mf][nf][1] + b1;
                sb[cl * 129 + rl + 8] = acc[mf][nf][2] + b0;
                sb[(cl + 1) * 129 + rl + 8] = acc[mf][nf][3] + b1;
            }
        __syncthreads();
        const int col = tid >> 1;
        const int half = (tid & 1) * 64;
        size_t base = (size_t)(nBase + col) * SEQ + mBase + half;
#pragma unroll
        for (int r = 0; r < 64; r += 2) {
            float x0 = sb[col * 129 + half + r];
            float x1 = sb[col * 129 + half + r + 1];
            *reinterpret_cast<__half2*>(&Ch[base + r]) =
                __half2(__float2half_rn(x0), __float2half_rn(x1));
        }
    }
}

// --------- register-resident softmax(scale*scores) + bias -> fp16 ------------
// 256 threads, 16 values/thread held in registers across all phases.
// Reductions: warp shuffle + 8-word smem stage; 2 block barriers total.
__global__ __launch_bounds__(256)
void softmax_bias_f16(const fp16* __restrict__ sc, const float* __restrict__ bias,
                      fp16* __restrict__ ah, float scale) {
    __shared__ float redmax[8];
    __shared__ float redsum[8];
    const int row = blockIdx.x;
    const int tid = threadIdx.x;
    const int wid = tid >> 5;
    const int lane = tid & 31;
    const fp16* rp = sc + (size_t)row * SEQ;
    const float* bp = bias + (size_t)row * SEQ;

    // load 16 values (two 16B segments, coalesced), convert + scale
    float v[16];
    float lmax = -1e30f;
#pragma unroll
    for (int seg = 0; seg < 2; seg++) {
        const int idx = seg * 2048 + tid * 8;
        uint4 raw = *reinterpret_cast<const uint4*>(rp + idx);
        const __half2* h = reinterpret_cast<const __half2*>(&raw);
#pragma unroll
        for (int j = 0; j < 4; j++) {
            float2 f = __half22float2(h[j]);
            v[seg * 8 + 2 * j] = f.x * scale;
            v[seg * 8 + 2 * j + 1] = f.y * scale;
        }
    }
#pragma unroll
    for (int i = 0; i < 16; i++) lmax = fmaxf(lmax, v[i]);
#pragma unroll
    for (int s = 16; s > 0; s >>= 1)
        lmax = fmaxf(lmax, __shfl_xor_sync(0xFFFFFFFFu, lmax, s));
    if (lane == 0) redmax[wid] = lmax;
    __syncthreads();
    float mx = redmax[0];
#pragma unroll
    for (int w = 1; w < 8; w++) mx = fmaxf(mx, redmax[w]);

    // exp in registers + sum
    float lsum = 0.f;
#pragma unroll
    for (int i = 0; i < 16; i++) {
        v[i] = __expf(v[i] - mx);
        lsum += v[i];
    }
#pragma unroll
    for (int s = 16; s > 0; s >>= 1)
        lsum += __shfl_xor_sync(0xFFFFFFFFu, lsum, s);
    if (lane == 0) redsum[wid] = lsum;
    __syncthreads();
    float tot = redsum[0];
#pragma unroll
    for (int w = 1; w < 8; w++) tot += redsum[w];
    const float inv = 1.0f / tot;

    // normalize + bias + fp16 store
#pragma unroll
    for (int seg = 0; seg < 2; seg++) {
        const int idx = seg * 2048 + tid * 8;
        float4 b0 = *reinterpret_cast<const float4*>(bp + idx);
        float4 b1 = *reinterpret_cast<const float4*>(bp + idx + 4);
        const float* vv = v + seg * 8;
        __half2 hv[4];
        hv[0] = __half2(__float2half_rn(vv[0] * inv + b0.x),
                        __float2half_rn(vv[1] * inv + b0.y));
        hv[1] = __half2(__float2half_rn(vv[2] * inv + b0.z),
                        __float2half_rn(vv[3] * inv + b0.w));
        hv[2] = __half2(__float2half_rn(vv[4] * inv + b1.x),
                        __float2half_rn(vv[5] * inv + b1.y));
        hv[3] = __half2(__float2half_rn(vv[6] * inv + b1.z),
                        __float2half_rn(vv[7] * inv + b1.w));
        *reinterpret_cast<uint4*>(ah + (size_t)row * SEQ + idx) =
            *reinterpret_cast<uint4*>(hv);
    }
}

// ---------------------------------------------------------------------------
extern "C" void kernel_launch(void* const* d_in, const int* in_sizes, int n_in,
                              void* d_out, int out_size) {
    const float* q = (const float*)d_in[0];
    const float* k = (const float*)d_in[1];
    const float* v = (const float*)d_in[2];
    const float* bias = (const float*)d_in[3];
    const float* Wq = (const float*)d_in[4];
    const float* bq = (const float*)d_in[5];
    const float* Wk = (const float*)d_in[6];
    const float* bk = (const float*)d_in[7];
    const float* Wv = (const float*)d_in[8];
    const float* bv = (const float*)d_in[9];
    float* out = (float*)d_out;

    fp16 *q16, *k16, *v16, *Wq16, *Wk16, *Wv16;
    fp16 *qp16, *kp16, *vt16, *sc16, *a16;
    cudaGetSymbolAddress((void**)&q16, g_q16);   cudaGetSymbolAddress((void**)&k16, g_k16);
    cudaGetSymbolAddress((void**)&v16, g_v16);
    cudaGetSymbolAddress((void**)&Wq16, g_Wq16); cudaGetSymbolAddress((void**)&Wk16, g_Wk16);
    cudaGetSymbolAddress((void**)&Wv16, g_Wv16);
    cudaGetSymbolAddress((void**)&qp16, g_qp16); cudaGetSymbolAddress((void**)&kp16, g_kp16);
    cudaGetSymbolAddress((void**)&vt16, g_vt16); cudaGetSymbolAddress((void**)&sc16, g_sc16);
    cudaGetSymbolAddress((void**)&a16, g_a16);

    cudaFuncSetAttribute(gemm_mma<0>, cudaFuncAttributeMaxDynamicSharedMemorySize, SMEM_SZ);
    cudaFuncSetAttribute(gemm_mma<1>, cudaFuncAttributeMaxDynamicSharedMemorySize, SMEM_SZ);
    cudaFuncSetAttribute(gemm_mma<2>, cudaFuncAttributeMaxDynamicSharedMemorySize, SMEM_SZ);
    cudaFuncSetAttribute(gemm_mma<3>, cudaFuncAttributeMaxDynamicSharedMemorySize, SMEM_SZ);

    // one-time side streams + events (validated fork/join pattern, round 12)
    static cudaStream_t s1 = nullptr, s2 = nullptr;
    static cudaEvent_t e0 = nullptr, e1 = nullptr, e2 = nullptr;
    if (!s1) {
        cudaStreamCreateWithFlags(&s1, cudaStreamNonBlocking);
        cudaStreamCreateWithFlags(&s2, cudaStreamNonBlocking);
        cudaEventCreateWithFlags(&e0, cudaEventDisableTiming);
        cudaEventCreateWithFlags(&e1, cudaEventDisableTiming);
        cudaEventCreateWithFlags(&e2, cudaEventDisableTiming);
    }

    const float scale = 0.03125f;  // 1024^-0.5  (applied in softmax)
    dim3 blk(256);

    // one batched convert launch: q,k,v (big) + Wq,Wk,Wv (small)  [stream 0]
    const int nBig = SEQ * DIM / 4, nSmall = DIM * DIM / 4;
    cvt6_kernel<<<dim3(nBig / 256, 6), blk>>>(q, k, v, Wq, Wk, Wv,
                                              q16, k16, v16, Wq16, Wk16, Wv16,
                                              nBig, nSmall);
    cudaEventRecord(e0, 0);

    dim3 gProj(DIM / 128, SEQ / 128);
    // q-projection on main stream
    gemm_mma<1><<<gProj, blk, SMEM_SZ>>>(q16, Wq16, bq, nullptr, qp16, DIM, DIM);
    // k-projection on s1 (concurrent with q)
    cudaStreamWaitEvent(s1, e0, 0);
    gemm_mma<1><<<gProj, blk, SMEM_SZ, s1>>>(k16, Wk16, bk, nullptr, kp16, DIM, DIM);
    cudaEventRecord(e1, s1);
    // v-projection on s2 (concurrent with q/k AND with scores/softmax below)
    cudaStreamWaitEvent(s2, e0, 0);
    gemm_mma<2><<<gProj, blk, SMEM_SZ, s2>>>(v16, Wv16, bv, nullptr, vt16, DIM, DIM);
    cudaEventRecord(e2, s2);

    // scores = qp @ kp^T -> fp16 (needs q-proj [stream order] + k-proj [event])
    cudaStreamWaitEvent(0, e1, 0);
    dim3 gScore(SEQ / 128, SEQ / 128);
    gemm_mma<3><<<gScore, blk, SMEM_SZ>>>(qp16, kp16, nullptr, nullptr, sc16,
                                          SEQ, DIM);

    // softmax(scale * scores) + bias -> fp16 att (register-resident)
    softmax_bias_f16<<<SEQ, blk>>>(sc16, bias, a16, scale);

    // out = att @ vp (needs v-proj via event)
    cudaStreamWaitEvent(0, e2, 0);
    dim3 gOut(DIM / 128, SEQ / 128);
    gemm_mma<0><<<gOut, blk, SMEM_SZ>>>(a16, vt16, nullptr, out, nullptr,
                                        DIM, SEQ);
}